// round 2
// baseline (speedup 1.0000x reference)
#include <cuda_runtime.h>
#include <cstdint>

// Spatial masked-pool-gate, single streaming pass:
//   xp = pad(x, 110->112); pooled = 4x4 sumpool(xp * mask);
//   out = (pooled > 0) ? xp : 0, cropped to 110x110.
//
// One thread per 4x4 patch; x kept in registers between the pool and the
// gated store. Mask rows (112 floats) are always float4-aligned. x/out rows
// (110 floats): EVEN rows are 16B-aligned at patch columns -> float4;
// odd rows are 8B-aligned -> float2 pairs. Streaming cache hints throughout.

namespace {
constexpr int HIN  = 110;
constexpr int HPAD = 112;
constexpr int PP   = 28;               // patches per side (112/4)
constexpr int NCH  = 64 * 64;
constexpr int CH_X = HIN * HIN;        // 12100
constexpr int CH_M = HPAD * HPAD;      // 12544
}

__global__ __launch_bounds__(256)
void spatial_gate_kernel(const float* __restrict__ x,
                         const float* __restrict__ mask,
                         float* __restrict__ out)
{
    const int p  = blockIdx.x * 256 + threadIdx.x;   // exact grid, no guard
    const int pc = p % PP;
    const int t  = p / PP;
    const int pr = t % PP;
    const int ch = t / PP;

    const float* __restrict__ xc = x    + (size_t)ch * CH_X;
    const float* __restrict__ mc = mask + (size_t)ch * CH_M;
    float*       __restrict__ oc = out  + (size_t)ch * CH_X;

    const int c0 = pc * 4;
    const int r0 = pr * 4;                 // always even
    const bool full_c = (c0 + 4 <= HIN);   // false only for pc == 27

    float4 xv[4];
    float sum = 0.0f;

    #pragma unroll
    for (int i = 0; i < 4; ++i) {
        const int row = r0 + i;
        if (row < HIN) {
            const float* xr = xc + row * HIN + c0;
            const float4 mv = __ldcs(reinterpret_cast<const float4*>(mc + row * HPAD + c0));
            if (full_c) {
                float4 v;
                if ((i & 1) == 0) {
                    // even row: 16B-aligned -> single 128-bit load
                    v = __ldcs(reinterpret_cast<const float4*>(xr));
                } else {
                    const float2 a = __ldcs(reinterpret_cast<const float2*>(xr));
                    const float2 b = __ldcs(reinterpret_cast<const float2*>(xr + 2));
                    v.x = a.x; v.y = a.y; v.z = b.x; v.w = b.y;
                }
                xv[i] = v;
                sum += v.x * mv.x;
                sum += v.y * mv.y;
                sum += v.z * mv.z;
                sum += v.w * mv.w;
            } else {
                const float2 a = __ldcs(reinterpret_cast<const float2*>(xr));
                xv[i].x = a.x; xv[i].y = a.y;
                sum += a.x * mv.x;
                sum += a.y * mv.y;
            }
        }
    }

    const float f = (sum > 0.0f) ? 1.0f : 0.0f;

    #pragma unroll
    for (int i = 0; i < 4; ++i) {
        const int row = r0 + i;
        if (row < HIN) {
            float* orow = oc + row * HIN + c0;
            if (full_c) {
                if ((i & 1) == 0) {
                    float4 v;
                    v.x = xv[i].x * f; v.y = xv[i].y * f;
                    v.z = xv[i].z * f; v.w = xv[i].w * f;
                    __stcs(reinterpret_cast<float4*>(orow), v);
                } else {
                    float2 a, b;
                    a.x = xv[i].x * f; a.y = xv[i].y * f;
                    b.x = xv[i].z * f; b.y = xv[i].w * f;
                    __stcs(reinterpret_cast<float2*>(orow), a);
                    __stcs(reinterpret_cast<float2*>(orow + 2), b);
                }
            } else {
                float2 a;
                a.x = xv[i].x * f; a.y = xv[i].y * f;
                __stcs(reinterpret_cast<float2*>(orow), a);
            }
        }
    }
}

extern "C" void kernel_launch(void* const* d_in, const int* in_sizes, int n_in,
                              void* d_out, int out_size)
{
    const float* x    = (const float*)d_in[0];
    const float* mask = (const float*)d_in[1];
    float* out = (float*)d_out;

    const int total_patches = NCH * PP * PP;   // 3,211,264
    const int blocks = total_patches / 256;    // 12,544 exact
    spatial_gate_kernel<<<blocks, 256>>>(x, mask, out);
}

// round 5
// speedup vs baseline: 1.0028x; 1.0028x over previous
#include <cuda_runtime.h>
#include <cstdint>

// Spatial masked-pool-gate, single streaming pass:
//   xp = pad(x, 110->112); pooled = 4x4 sumpool(xp * mask);
//   out = (pooled > 0) ? xp : 0, cropped to 110x110.
//
// One thread per 4x4 patch; x kept in registers between the pool and the
// gated store. Mask rows (112 floats) are float4-aligned at patch columns.
// x/out rows (110 floats): EVEN rows are 16B-aligned at patch columns ->
// float4; odd rows are 8B-aligned -> float2 pairs. Default cache policy
// (streaming hints measurably hurt L2 write coalescing here — R2 evidence).

namespace {
constexpr int HIN  = 110;
constexpr int HPAD = 112;
constexpr int PP   = 28;               // patches per side (112/4)
constexpr int NCH  = 64 * 64;
constexpr int CH_X = HIN * HIN;        // 12100
constexpr int CH_M = HPAD * HPAD;      // 12544
}

__global__ __launch_bounds__(256)
void spatial_gate_kernel(const float* __restrict__ x,
                         const float* __restrict__ mask,
                         float* __restrict__ out)
{
    const int p  = blockIdx.x * 256 + threadIdx.x;   // exact grid, no guard
    const int pc = p % PP;
    const int t  = p / PP;
    const int pr = t % PP;
    const int ch = t / PP;

    const float* __restrict__ xc = x    + (size_t)ch * CH_X;
    const float* __restrict__ mc = mask + (size_t)ch * CH_M;
    float*       __restrict__ oc = out  + (size_t)ch * CH_X;

    const int c0 = pc * 4;
    const int r0 = pr * 4;                 // always even
    const bool full_c = (c0 + 4 <= HIN);   // false only for pc == 27

    float4 xv[4];
    float sum = 0.0f;

    #pragma unroll
    for (int i = 0; i < 4; ++i) {
        const int row = r0 + i;
        if (row < HIN) {
            const float* xr = xc + row * HIN + c0;
            const float4 mv = *reinterpret_cast<const float4*>(mc + row * HPAD + c0);
            if (full_c) {
                float4 v;
                if ((i & 1) == 0) {
                    // even row: 16B-aligned -> single 128-bit load
                    v = *reinterpret_cast<const float4*>(xr);
                } else {
                    const float2 a = *reinterpret_cast<const float2*>(xr);
                    const float2 b = *reinterpret_cast<const float2*>(xr + 2);
                    v.x = a.x; v.y = a.y; v.z = b.x; v.w = b.y;
                }
                xv[i] = v;
                sum += v.x * mv.x;
                sum += v.y * mv.y;
                sum += v.z * mv.z;
                sum += v.w * mv.w;
            } else {
                const float2 a = *reinterpret_cast<const float2*>(xr);
                xv[i].x = a.x; xv[i].y = a.y;
                sum += a.x * mv.x;
                sum += a.y * mv.y;
            }
        }
    }

    const float f = (sum > 0.0f) ? 1.0f : 0.0f;

    #pragma unroll
    for (int i = 0; i < 4; ++i) {
        const int row = r0 + i;
        if (row < HIN) {
            float* orow = oc + row * HIN + c0;
            if (full_c) {
                if ((i & 1) == 0) {
                    float4 v;
                    v.x = xv[i].x * f; v.y = xv[i].y * f;
                    v.z = xv[i].z * f; v.w = xv[i].w * f;
                    *reinterpret_cast<float4*>(orow) = v;
                } else {
                    float2 a, b;
                    a.x = xv[i].x * f; a.y = xv[i].y * f;
                    b.x = xv[i].z * f; b.y = xv[i].w * f;
                    *reinterpret_cast<float2*>(orow) = a;
                    *reinterpret_cast<float2*>(orow + 2) = b;
                }
            } else {
                float2 a;
                a.x = xv[i].x * f; a.y = xv[i].y * f;
                *reinterpret_cast<float2*>(orow) = a;
            }
        }
    }
}

extern "C" void kernel_launch(void* const* d_in, const int* in_sizes, int n_in,
                              void* d_out, int out_size)
{
    const float* x    = (const float*)d_in[0];
    const float* mask = (const float*)d_in[1];
    float* out = (float*)d_out;

    const int total_patches = NCH * PP * PP;   // 3,211,264
    const int blocks = total_patches / 256;    // 12,544 exact
    spatial_gate_kernel<<<blocks, 256>>>(x, mask, out);
}

// round 8
// speedup vs baseline: 1.0294x; 1.0266x over previous
#include <cuda_runtime.h>
#include <cstdint>

// Spatial masked-pool-gate, single streaming pass (CONVERGED — R1 config):
//   xp = pad(x, 110->112); pooled = 4x4 sumpool(xp * mask);
//   out = (pooled > 0) ? xp : 0, cropped to 110x110.
//
// One thread per 4x4 patch; x kept in registers between the pool and the
// gated store (x read exactly once -> traffic floor ~598 MB).
// Homogeneous float2 x/out accesses + float4 mask, DEFAULT cache policy:
// measured best (DRAM 79.9% of spec = the mixed-RW HBM ceiling).
// Wider loads (R5) and streaming hints (R2) both measured slower.

namespace {
constexpr int HIN  = 110;
constexpr int HPAD = 112;
constexpr int PP   = 28;               // patches per side (112/4)
constexpr int NCH  = 64 * 64;          // N*C channels
constexpr int CH_X = HIN * HIN;        // 12100 floats per channel (x/out)
constexpr int CH_M = HPAD * HPAD;      // 12544 floats per channel (mask)
}

__global__ __launch_bounds__(256)
void spatial_gate_kernel(const float* __restrict__ x,
                         const float* __restrict__ mask,
                         float* __restrict__ out)
{
    const int p  = blockIdx.x * 256 + threadIdx.x;   // exact grid, no guard
    const int pc = p % PP;
    const int t  = p / PP;
    const int pr = t % PP;
    const int ch = t / PP;

    const float* __restrict__ xc = x    + (size_t)ch * CH_X;
    const float* __restrict__ mc = mask + (size_t)ch * CH_M;
    float*       __restrict__ oc = out  + (size_t)ch * CH_X;

    const int c0 = pc * 4;
    const int r0 = pr * 4;
    const bool full_c = (c0 + 4 <= HIN);   // false only for pc == 27 (cols 108..111)

    float xv[4][4];
    float sum = 0.0f;

    #pragma unroll
    for (int i = 0; i < 4; ++i) {
        const int row = r0 + i;
        if (row < HIN) {
            const float*  xr = xc + row * HIN + c0;
            const float4  mv = *reinterpret_cast<const float4*>(mc + row * HPAD + c0);
            const float2  a  = *reinterpret_cast<const float2*>(xr);
            xv[i][0] = a.x; xv[i][1] = a.y;
            sum += a.x * mv.x;
            sum += a.y * mv.y;
            if (full_c) {
                const float2 b = *reinterpret_cast<const float2*>(xr + 2);
                xv[i][2] = b.x; xv[i][3] = b.y;
                sum += b.x * mv.z;
                sum += b.y * mv.w;
            }
        }
    }

    const float f = (sum > 0.0f) ? 1.0f : 0.0f;

    #pragma unroll
    for (int i = 0; i < 4; ++i) {
        const int row = r0 + i;
        if (row < HIN) {
            float* orow = oc + row * HIN + c0;
            float2 a;
            a.x = xv[i][0] * f;
            a.y = xv[i][1] * f;
            *reinterpret_cast<float2*>(orow) = a;
            if (full_c) {
                float2 b;
                b.x = xv[i][2] * f;
                b.y = xv[i][3] * f;
                *reinterpret_cast<float2*>(orow + 2) = b;
            }
        }
    }
}

extern "C" void kernel_launch(void* const* d_in, const int* in_sizes, int n_in,
                              void* d_out, int out_size)
{
    const float* x    = (const float*)d_in[0];
    const float* mask = (const float*)d_in[1];
    // d_in[2] is p_size (== 4), compile-time constant here.
    float* out = (float*)d_out;

    const int total_patches = NCH * PP * PP;       // 3,211,264
    const int blocks = total_patches / 256;        // 12,544 exact
    spatial_gate_kernel<<<blocks, 256>>>(x, mask, out);
}